// round 15
// baseline (speedup 1.0000x reference)
#include <cuda_runtime.h>
#include <cstdint>

// ---------------------------------------------------------------------------
// Scratch
// ---------------------------------------------------------------------------
__device__ int    g_fps_idx[8 * 4096];
__device__ float4 g_sorted[8 * 8192];     // per-batch spatially sorted points

typedef unsigned long long u64;

// 8x8x8 Morton cell over [-4, 4]
__device__ __forceinline__ int cell_of(float x, float y, float z) {
    int cx = min(max((int)(x + 4.0f), 0), 7);
    int cy = min(max((int)(y + 4.0f), 0), 7);
    int cz = min(max((int)(z + 4.0f), 0), 7);
    return (cx & 1) | ((cy & 1) << 1) | ((cz & 1) << 2)
         | (((cx >> 1) & 1) << 3) | (((cy >> 1) & 1) << 4) | (((cz >> 1) & 1) << 5)
         | ((cx >> 2) << 6) | ((cy >> 2) << 7) | ((cz >> 2) << 8);
}

// Dummy kernel: three of these shift ncu's fixed capture slot (launch index
// 3) onto the level-1 FPS kernel.
__global__ void probe_align_kernel() {}

// ---------------------------------------------------------------------------
// Level-1 FPS: 256 threads (8 warps), K=32 pts/thread.
//
// Skeleton cost is linear in warp count (R11-measured), so 8 warps halves
// R12's issue share. Registers stay at ~75 (no R13-style spills) because
// coordinates are NOT register-resident: the (rare, bbox-pruned) update
// loop re-reads the thread's 32 sorted points via LDG.128 from g_sorted
// (L1-resident: smem is only ~4KB static, so pts 96KB + sorted 128KB fit
// the 228KB L1). Winner coords come from pts (orig-order) via 3 LDG.32.
//
// Exactness:
//  * distance math: verbatim scalar dx*dx+dy*dy+dz*dz (FMUL+FFMA contraction,
//    bit-proven vs reference since R1) and fminf chain.
//  * tie-break: per-point u64 key (dist_bits<<32)|(comp13<<19),
//    comp13 = 8191 - orig_idx. u64/staged-redux max == (value desc,
//    orig idx asc) == jnp.argmax first-occurrence (R7/R12-validated).
//  * skip test: monotone a*a+b*b+c*c bbox argument (R8-proven); a passing
//    warp's cached key stays exact, the winner's warp always fails (mind2=0).
//
// NESTED-FPS THEOREM (R12-proven): levels 2-4 FPS == identity; this is the
// only FPS kernel.
// ---------------------------------------------------------------------------
template <int N>
__global__ __launch_bounds__(256, 1)
void fps_kernel(const float* __restrict__ pts, int C, int npoints,
                int* __restrict__ idx_out, float4* __restrict__ sorted_g)
{
    constexpr int T = 256, NW = 8, K = 32, KP = 16;

    __shared__ u64 rkeypub[2][NW];
    __shared__ int hist[512];
    __shared__ int offs[512];

    const int b    = blockIdx.x;
    const int t    = threadIdx.x;
    const int lane = t & 31;
    const int wid  = t >> 5;

    const float* base = pts + (size_t)b * N * C;
    float4* sorted = sorted_g + (size_t)b * N;

    // ---- histogram over Morton cells ----
    hist[t] = 0; hist[t + 256] = 0;
    __syncthreads();
#pragma unroll
    for (int k = 0; k < K; ++k) {
        int i = t + k * T;
        const float* r = base + (size_t)i * C;
        atomicAdd(&hist[cell_of(r[0], r[1], r[2])], 1);
    }
    __syncthreads();
    if (t == 0) {
        int s = 0;
        for (int c = 0; c < 512; ++c) { offs[c] = s; s += hist[c]; }
    }
    __syncthreads();
    // ---- scatter to sorted global scratch (orig idx in .w) ----
#pragma unroll
    for (int k = 0; k < K; ++k) {
        int i = t + k * T;
        const float* r = base + (size_t)i * C;
        float xx = r[0], yy = r[1], zz = r[2];
        int pos = atomicAdd(&offs[cell_of(xx, yy, zz)], 1);
        sorted[pos] = make_float4(xx, yy, zz, __int_as_float(i));
    }
    __syncthreads();   // sorted[] visible block-wide (barrier fences gmem)

    // ---- one pass over own sorted points: d init (to point 0), comp pack,
    //      warp bbox. Coords are NOT kept in registers. ----
    float d[K];
    unsigned cpk[KP];                          // comp13 packed 2x16-bit
    float mnx = 1e30f, mny = 1e30f, mnz = 1e30f;
    float mxx = -1e30f, mxy = -1e30f, mxz = -1e30f;
    u64 bk = 0;
    {
        float px = base[0], py = base[1], pz = base[2];   // orig point 0
#pragma unroll
        for (int k = 0; k < K; ++k) {
            int slot = wid * (32 * K) + k * 32 + lane;
            float4 s = sorted[slot];
            float dx = s.x - px, dy = s.y - py, dz = s.z - pz;
            d[k] = dx * dx + dy * dy + dz * dz;
            unsigned comp = 8191u - (unsigned)__float_as_int(s.w);
            if (k & 1) cpk[k >> 1] |= comp << 16;
            else       cpk[k >> 1]  = comp;
            mnx = fminf(mnx, s.x); mxx = fmaxf(mxx, s.x);
            mny = fminf(mny, s.y); mxy = fmaxf(mxy, s.y);
            mnz = fminf(mnz, s.z); mxz = fmaxf(mxz, s.z);
            u64 key = ((u64)__float_as_uint(d[k]) << 32) | ((u64)comp << 19);
            if (key > bk) bk = key;
        }
    }
#pragma unroll
    for (int o = 16; o > 0; o >>= 1) {
        mnx = fminf(mnx, __shfl_xor_sync(0xffffffffu, mnx, o));
        mny = fminf(mny, __shfl_xor_sync(0xffffffffu, mny, o));
        mnz = fminf(mnz, __shfl_xor_sync(0xffffffffu, mnz, o));
        mxx = fmaxf(mxx, __shfl_xor_sync(0xffffffffu, mxx, o));
        mxy = fmaxf(mxy, __shfl_xor_sync(0xffffffffu, mxy, o));
        mxz = fmaxf(mxz, __shfl_xor_sync(0xffffffffu, mxz, o));
    }

    if (t == 0) idx_out[b * npoints] = 0;

    // stage-1 warp reduce of initial keys
    unsigned cm, ccomp;
    {
        unsigned ub = (unsigned)(bk >> 32);
        cm = __reduce_max_sync(0xffffffffu, ub);
        unsigned cd = (ub == cm) ? (unsigned)bk : 0u;
        ccomp = __reduce_max_sync(0xffffffffu, cd);
    }
    u64 wkey = ((u64)cm << 32) | (u64)ccomp;

    for (int it = 1; it < npoints; ++it) {
        const int p = it & 1;
        if (lane == 0) rkeypub[p][wid] = wkey;
        __syncthreads();

        // stage 2: reduce the 8 warp keys
        u64 kk = rkeypub[p][lane & (NW - 1)];
        unsigned vw = (unsigned)(kk >> 32);
        unsigned iw = (unsigned)kk;
        unsigned m2 = __reduce_max_sync(0xffffffffu, vw);
        unsigned c2 = (vw == m2) ? iw : 0u;
        unsigned comp2 = __reduce_max_sync(0xffffffffu, c2) >> 19;
        int bsel = 8191 - (int)comp2;               // ORIGINAL index

        if (t == 0) idx_out[b * npoints + it] = bsel;

        // winner coords from pts (orig order, L1-hot)
        const float* w = base + (size_t)bsel * C;
        float px = w[0], py = w[1], pz = w[2];

        // warp-uniform exact bbox skip test
        float ax = fmaxf(fmaxf(mnx - px, px - mxx), 0.f);
        float ay = fmaxf(fmaxf(mny - py, py - mxy), 0.f);
        float az = fmaxf(fmaxf(mnz - pz, pz - mxz), 0.f);
        float mind2 = ax * ax + ay * ay + az * az;
        if (mind2 >= __uint_as_float((unsigned)(wkey >> 32))) continue;

        // update: re-read own sorted points (LDG.128, L1-resident)
        u64 nbk = 0;
#pragma unroll 8
        for (int k = 0; k < K; ++k) {
            int slot = wid * (32 * K) + k * 32 + lane;
            float4 s = sorted[slot];
            float dx = s.x - px, dy = s.y - py, dz = s.z - pz;
            float nd = dx * dx + dy * dy + dz * dz;
            float dk = fminf(d[k], nd);
            d[k] = dk;
            unsigned comp = (cpk[k >> 1] >> ((k & 1) * 16)) & 0xFFFFu;
            u64 key = ((u64)__float_as_uint(dk) << 32) | ((u64)comp << 19);
            if (key > nbk) nbk = key;
        }
        unsigned ub = (unsigned)(nbk >> 32);
        cm = __reduce_max_sync(0xffffffffu, ub);
        unsigned cd = (ub == cm) ? (unsigned)nbk : 0u;
        ccomp = __reduce_max_sync(0xffffffffu, cd);
        wkey = ((u64)cm << 32) | (u64)ccomp;
    }
}

// ---------------------------------------------------------------------------
// Gather + pointwise 2-layer MLP + output assembly.
// IDENT=true: downsample row index == output row index (nested-FPS theorem).
// ---------------------------------------------------------------------------
template <int CPREV, int F, bool REPEAT, bool IDENT>
__global__ __launch_bounds__(256)
void mlp_kernel(const float* __restrict__ in, const int* __restrict__ idx,
                const float* __restrict__ w1, const float* __restrict__ b1,
                const float* __restrict__ w2, const float* __restrict__ b2,
                float* __restrict__ out, int n_in, int npoints)
{
    constexpr int PPB = 256 / F;
    constexpr int CIN = REPEAT ? 2 * CPREV : CPREV;

    __shared__ float row[PPB][CPREV];
    __shared__ float hsm[PPB][F];

    const int t  = threadIdx.x;
    const int lp = t / F;
    const int g  = t % F;
    const int gp = blockIdx.x * PPB + lp;
    const int b  = gp / npoints;
    const int pt = gp % npoints;

    const int src = IDENT ? pt : idx[b * npoints + pt];
    const float* r = in + ((size_t)b * n_in + src) * CPREV;
    if (g < CPREV) row[lp][g] = r[g];
    __syncthreads();

    float acc = b1[g];
#pragma unroll
    for (int c = 0; c < CIN; ++c)
        acc += row[lp][c % CPREV] * w1[c * F + g];
    hsm[lp][g] = fmaxf(acc, 0.0f);
    __syncthreads();

    float o = b2[g];
#pragma unroll
    for (int j = 0; j < F; ++j)
        o += hsm[lp][j] * w2[j * F + g];

    float* orow = out + ((size_t)b * npoints + pt) * F;
    orow[g] = (g < 3) ? row[lp][g] : o;
}

// ---------------------------------------------------------------------------
// Launch
// ---------------------------------------------------------------------------
extern "C" void kernel_launch(void* const* d_in, const int* in_sizes, int n_in_cnt,
                              void* d_out, int out_size)
{
    (void)in_sizes; (void)n_in_cnt; (void)out_size;

    const float* pts  = (const float*)d_in[0];
    const float* w1_1 = (const float*)d_in[1];
    const float* b1_1 = (const float*)d_in[2];
    const float* w2_1 = (const float*)d_in[3];
    const float* b2_1 = (const float*)d_in[4];
    const float* w1_2 = (const float*)d_in[5];
    const float* b1_2 = (const float*)d_in[6];
    const float* w2_2 = (const float*)d_in[7];
    const float* b2_2 = (const float*)d_in[8];
    const float* w1_3 = (const float*)d_in[9];
    const float* b1_3 = (const float*)d_in[10];
    const float* w2_3 = (const float*)d_in[11];
    const float* b2_3 = (const float*)d_in[12];
    const float* w1_4 = (const float*)d_in[13];
    const float* b1_4 = (const float*)d_in[14];
    const float* w2_4 = (const float*)d_in[15];
    const float* b2_4 = (const float*)d_in[16];

    float* out = (float*)d_out;
    const int B = 8;
    float* f1 = out;                        // [8,4096,16]
    float* f2 = out + 8 * 4096 * 16;        // [8,2048,32]
    float* f3 = f2 + 8 * 2048 * 32;         // [8,1024,64]
    float* f4 = f3 + 8 * 1024 * 64;         // [8, 512,128]

    static int*    idx_buf = nullptr;
    static float4* sort_buf = nullptr;
    if (!idx_buf)  cudaGetSymbolAddress((void**)&idx_buf,  g_fps_idx);
    if (!sort_buf) cudaGetSymbolAddress((void**)&sort_buf, g_sorted);

    // Slot shims: launch indices 0-2, so ncu's fixed capture slot (index 3)
    // lands on the level-1 FPS kernel.
    probe_align_kernel<<<1, 32>>>();
    probe_align_kernel<<<1, 32>>>();
    probe_align_kernel<<<1, 32>>>();

    // ---- Level 1: 8192 -> 4096 — the ONLY FPS run ----
    fps_kernel<8192><<<B, 256>>>(pts, 3, 4096, idx_buf, sort_buf);
    mlp_kernel<3, 16, true, false><<<(B * 4096) / 16, 256>>>(
        pts, idx_buf, w1_1, b1_1, w2_1, b2_1, f1, 8192, 4096);

    // ---- Levels 2-4: nested-FPS theorem -> identity downsample ----
    mlp_kernel<16, 32, false, true><<<(B * 2048) / 8, 256>>>(
        f1, idx_buf, w1_2, b1_2, w2_2, b2_2, f2, 4096, 2048);

    mlp_kernel<32, 64, false, true><<<(B * 1024) / 4, 256>>>(
        f2, idx_buf, w1_3, b1_3, w2_3, b2_3, f3, 2048, 1024);

    mlp_kernel<64, 128, false, true><<<(B * 512) / 2, 256>>>(
        f3, idx_buf, w1_4, b1_4, w2_4, b2_4, f4, 1024, 512);
}

// round 16
// speedup vs baseline: 3.7254x; 3.7254x over previous
#include <cuda_runtime.h>
#include <cstdint>

// ---------------------------------------------------------------------------
// Scratch
// ---------------------------------------------------------------------------
__device__ int    g_fps_idx[8 * 4096];
__device__ float4 g_sorted[8 * 8192];     // per-batch spatially sorted points

typedef unsigned long long u64;

// Packed f32x2 add (per-lane IEEE rn — proven bitwise == scalar FADD in R6)
__device__ __forceinline__ u64 pack2(float a, float b) {
    u64 r; asm("mov.b64 %0, {%1, %2};" : "=l"(r) : "f"(a), "f"(b)); return r;
}
__device__ __forceinline__ void unpack2(u64 v, float& a, float& b) {
    asm("mov.b64 {%0, %1}, %2;" : "=f"(a), "=f"(b) : "l"(v));
}
__device__ __forceinline__ u64 add2(u64 a, u64 b) {
    u64 r; asm("add.rn.f32x2 %0, %1, %2;" : "=l"(r) : "l"(a), "l"(b)); return r;
}

// 8x8x8 Morton cell over [-4, 4]
__device__ __forceinline__ int cell_of(float x, float y, float z) {
    int cx = min(max((int)(x + 4.0f), 0), 7);
    int cy = min(max((int)(y + 4.0f), 0), 7);
    int cz = min(max((int)(z + 4.0f), 0), 7);
    return (cx & 1) | ((cy & 1) << 1) | ((cz & 1) << 2)
         | (((cx >> 1) & 1) << 3) | (((cy >> 1) & 1) << 4) | (((cz >> 1) & 1) << 5)
         | ((cx >> 2) << 6) | ((cy >> 2) << 7) | ((cz >> 2) << 8);
}

// Dummy kernel: three of these shift ncu's fixed capture slot (launch index
// 3) onto the level-1 FPS kernel.
__global__ void probe_align_kernel() {}

// ---------------------------------------------------------------------------
// Level-1 FPS with EXACT PAIR-PICKING. 512 threads (16 warps), K=16.
//
// Keys: u64 (dist_bits<<32)|comp13, comp13 = 8191 - orig_idx. u64 max ==
// (value desc, orig idx asc) == jnp.argmax first-occurrence (R7/R12-proven).
// Each warp caches its TOP-2 keys; the 32-key pool (16 warps x 2) provably
// contains the block top-2 (block #2 is either in the block #1's warp -> its
// k2, or another warp -> that warp's k1).
//
// Pair theorem (exact): let key1=(v1,q1), key2=(v2,q2) be block top-2.
// If dist2(q2,q1) >= v2 (float >=), then after picking q1 the next pick is
// exactly q2: fminf(d(q2), nd) = d(q2) = v2; every other point p has
// min(d(p), nd(p)) <= d(p) <= v2, and any p tying at v2 requires
// d(p)=v2 & nd(p)>=d(p) — among those, q2 has min orig idx by key order.
// Merged update min(min(d,nd1),nd2) == two sequential reference updates
// (fminf is an exact min, same order). Per-pivot bbox skip: if
// mind2(bbox,q) >= warp max d, fminf is a no-op for every point of the
// warp (monotone a*a+b*b+c*c argument, R8-proven) -> update only with
// failing pivots is bitwise identical.
//
// NESTED-FPS THEOREM (R12-proven): levels 2-4 FPS == identity.
// ---------------------------------------------------------------------------
template <int N>
__global__ __launch_bounds__(512, 1)
void fps_kernel(const float* __restrict__ pts, int C, int npoints,
                int* __restrict__ idx_out, float4* __restrict__ sorted_g)
{
    constexpr int T = 512, NW = 16, K = 16, KP = 8;

    extern __shared__ float4 sxyz[];          // N entries, ORIGINAL order
    __shared__ u64 pub[2][2][NW];             // [parity][k1/k2][wid]
    __shared__ int hist[512];
    __shared__ int offs[512];

    const int b    = blockIdx.x;
    const int t    = threadIdx.x;
    const int lane = t & 31;
    const int wid  = t >> 5;

    const float* base = pts + (size_t)b * N * C;
    float4* sorted = sorted_g + (size_t)b * N;

    // ---- load orig-order copy + cell histogram ----
    hist[t] = 0;
    __syncthreads();
#pragma unroll
    for (int k = 0; k < K; ++k) {
        int i = t + k * T;
        const float* r = base + (size_t)i * C;
        float xx = r[0], yy = r[1], zz = r[2];
        sxyz[i] = make_float4(xx, yy, zz, 0.f);
        atomicAdd(&hist[cell_of(xx, yy, zz)], 1);
    }
    __syncthreads();
    if (t == 0) {
        int s = 0;
        for (int c = 0; c < 512; ++c) { offs[c] = s; s += hist[c]; }
    }
    __syncthreads();
#pragma unroll
    for (int k = 0; k < K; ++k) {
        int i = t + k * T;
        float4 q = sxyz[i];
        int pos = atomicAdd(&offs[cell_of(q.x, q.y, q.z)], 1);
        sorted[pos] = make_float4(q.x, q.y, q.z, __int_as_float(i));
    }
    __syncthreads();

    // ---- load my sorted points; pack comp13 2x16-bit ----
    float xr[K], yr[K], zr[K], d[K];
    unsigned cpk[KP];
#pragma unroll
    for (int k = 0; k < K; ++k) {
        int slot = wid * (32 * K) + k * 32 + lane;
        float4 s = sorted[slot];
        xr[k] = s.x; yr[k] = s.y; zr[k] = s.z;
        unsigned comp = 8191u - (unsigned)__float_as_int(s.w);
        if (k & 1) cpk[k >> 1] |= comp << 16;
        else       cpk[k >> 1]  = comp;
    }

    // ---- warp bbox ----
    float mnx = 1e30f, mny = 1e30f, mnz = 1e30f;
    float mxx = -1e30f, mxy = -1e30f, mxz = -1e30f;
#pragma unroll
    for (int k = 0; k < K; ++k) {
        mnx = fminf(mnx, xr[k]); mxx = fmaxf(mxx, xr[k]);
        mny = fminf(mny, yr[k]); mxy = fmaxf(mxy, yr[k]);
        mnz = fminf(mnz, zr[k]); mxz = fmaxf(mxz, zr[k]);
    }
#pragma unroll
    for (int o = 16; o > 0; o >>= 1) {
        mnx = fminf(mnx, __shfl_xor_sync(0xffffffffu, mnx, o));
        mny = fminf(mny, __shfl_xor_sync(0xffffffffu, mny, o));
        mnz = fminf(mnz, __shfl_xor_sync(0xffffffffu, mnz, o));
        mxx = fmaxf(mxx, __shfl_xor_sync(0xffffffffu, mxx, o));
        mxy = fmaxf(mxy, __shfl_xor_sync(0xffffffffu, mxy, o));
        mxz = fmaxf(mxz, __shfl_xor_sync(0xffffffffu, mxz, o));
    }

    // ---- packed coord registers ----
    u64 xp[KP], yp[KP], zp[KP];
#pragma unroll
    for (int j = 0; j < KP; ++j) {
        xp[j] = pack2(xr[2 * j], xr[2 * j + 1]);
        yp[j] = pack2(yr[2 * j], yr[2 * j + 1]);
        zp[j] = pack2(zr[2 * j], zr[2 * j + 1]);
    }

    if (t == 0) idx_out[b * npoints] = 0;

    // ---- initial distances to point 0 (verbatim scalar) + thread top-2 ----
    u64 tb1 = 0, tb2 = 0;
    {
        float4 q = sxyz[0];
        float px = q.x, py = q.y, pz = q.z;
#pragma unroll
        for (int k = 0; k < K; ++k) {
            float dx = xr[k] - px, dy = yr[k] - py, dz = zr[k] - pz;
            d[k] = dx * dx + dy * dy + dz * dz;
            unsigned comp = (cpk[k >> 1] >> ((k & 1) * 16)) & 0xFFFFu;
            u64 key = ((u64)__float_as_uint(d[k]) << 32) | (u64)comp;
            if (key > tb1) { tb2 = tb1; tb1 = key; }
            else if (key > tb2) { tb2 = key; }
        }
    }
    // ---- warp top-2 keys ----
    u64 wk1, wk2;
    {
        unsigned h = (unsigned)(tb1 >> 32);
        unsigned m = __reduce_max_sync(0xffffffffu, h);
        unsigned c = __reduce_max_sync(0xffffffffu, (h == m) ? (unsigned)tb1 : 0u);
        wk1 = ((u64)m << 32) | (u64)c;
        u64 contrib = (tb1 == wk1) ? tb2 : tb1;
        unsigned h2 = (unsigned)(contrib >> 32);
        unsigned m2 = __reduce_max_sync(0xffffffffu, h2);
        unsigned c2 = __reduce_max_sync(0xffffffffu, (h2 == m2) ? (unsigned)contrib : 0u);
        wk2 = ((u64)m2 << 32) | (u64)c2;
    }

    int it = 1, rc = 0;
    while (it < npoints) {
        const int p = rc & 1; rc++;
        if (lane == 0) { pub[p][0][wid] = wk1; pub[p][1][wid] = wk2; }
        __syncthreads();

        // stage 2 over the 32-key pool: block top-1, then masked top-2
        u64 kk = ((const u64*)pub[p])[lane];
        unsigned hi = (unsigned)(kk >> 32), lo = (unsigned)kk;
        unsigned m1v = __reduce_max_sync(0xffffffffu, hi);
        unsigned c1  = __reduce_max_sync(0xffffffffu, (hi == m1v) ? lo : 0u);
        bool iswin = (hi == m1v) && (lo == c1);
        unsigned hiB = iswin ? 0u : hi;
        unsigned loB = iswin ? 0u : lo;
        unsigned m2v = __reduce_max_sync(0xffffffffu, hiB);
        unsigned c2  = __reduce_max_sync(0xffffffffu, (hiB == m2v) ? loB : 0u);
        int bsel1 = 8191 - (int)c1;
        int bsel2 = 8191 - (int)c2;

        float4 q1 = sxyz[bsel1];
        float4 q2 = sxyz[bsel2];

        // pair condition (exact): dist2(q2,q1) >= d(q2)
        float ddx = q2.x - q1.x, ddy = q2.y - q1.y, ddz = q2.z - q1.z;
        float nd21 = ddx * ddx + ddy * ddy + ddz * ddz;
        bool pair = (it + 1 < npoints) && (nd21 >= __uint_as_float(m2v));

        if (t == 0) {
            idx_out[b * npoints + it] = bsel1;
            if (pair) idx_out[b * npoints + it + 1] = bsel2;
        }
        it += pair ? 2 : 1;

        // per-pivot exact bbox skip tests
        float wk1v = __uint_as_float((unsigned)(wk1 >> 32));
        float a0 = fmaxf(fmaxf(mnx - q1.x, q1.x - mxx), 0.f);
        float a1 = fmaxf(fmaxf(mny - q1.y, q1.y - mxy), 0.f);
        float a2 = fmaxf(fmaxf(mnz - q1.z, q1.z - mxz), 0.f);
        bool f1 = (a0 * a0 + a1 * a1 + a2 * a2) < wk1v;
        bool f2 = false;
        if (pair) {
            float b0 = fmaxf(fmaxf(mnx - q2.x, q2.x - mxx), 0.f);
            float b1f = fmaxf(fmaxf(mny - q2.y, q2.y - mxy), 0.f);
            float b2f = fmaxf(fmaxf(mnz - q2.z, q2.z - mxz), 0.f);
            f2 = (b0 * b0 + b1f * b1f + b2f * b2f) < wk1v;
        }
        if (!(f1 || f2)) continue;

        // update with failing pivots (q1 first, then q2 — reference order)
        const u64 nx1 = pack2(-q1.x, -q1.x), ny1 = pack2(-q1.y, -q1.y), nz1 = pack2(-q1.z, -q1.z);
        const u64 nx2 = pack2(-q2.x, -q2.x), ny2 = pack2(-q2.y, -q2.y), nz2 = pack2(-q2.z, -q2.z);
        tb1 = 0; tb2 = 0;
#pragma unroll
        for (int j = 0; j < KP; ++j) {
            float dk0 = d[2 * j], dk1 = d[2 * j + 1];
            if (f1) {
                float dx0, dx1, dy0, dy1, dz0, dz1;
                unpack2(add2(xp[j], nx1), dx0, dx1);
                unpack2(add2(yp[j], ny1), dy0, dy1);
                unpack2(add2(zp[j], nz1), dz0, dz1);
                float nd0 = dx0 * dx0 + dy0 * dy0 + dz0 * dz0;
                float nd1 = dx1 * dx1 + dy1 * dy1 + dz1 * dz1;
                dk0 = fminf(dk0, nd0);
                dk1 = fminf(dk1, nd1);
            }
            if (f2) {
                float dx0, dx1, dy0, dy1, dz0, dz1;
                unpack2(add2(xp[j], nx2), dx0, dx1);
                unpack2(add2(yp[j], ny2), dy0, dy1);
                unpack2(add2(zp[j], nz2), dz0, dz1);
                float nd0 = dx0 * dx0 + dy0 * dy0 + dz0 * dz0;
                float nd1 = dx1 * dx1 + dy1 * dy1 + dz1 * dz1;
                dk0 = fminf(dk0, nd0);
                dk1 = fminf(dk1, nd1);
            }
            d[2 * j]     = dk0;
            d[2 * j + 1] = dk1;
            u64 key0 = ((u64)__float_as_uint(dk0) << 32) | (u64)(cpk[j] & 0xFFFFu);
            u64 key1 = ((u64)__float_as_uint(dk1) << 32) | (u64)(cpk[j] >> 16);
            if (key0 > tb1) { tb2 = tb1; tb1 = key0; } else if (key0 > tb2) tb2 = key0;
            if (key1 > tb1) { tb2 = tb1; tb1 = key1; } else if (key1 > tb2) tb2 = key1;
        }
        // warp top-2 redux
        {
            unsigned h = (unsigned)(tb1 >> 32);
            unsigned m = __reduce_max_sync(0xffffffffu, h);
            unsigned c = __reduce_max_sync(0xffffffffu, (h == m) ? (unsigned)tb1 : 0u);
            wk1 = ((u64)m << 32) | (u64)c;
            u64 contrib = (tb1 == wk1) ? tb2 : tb1;
            unsigned h2 = (unsigned)(contrib >> 32);
            unsigned m2 = __reduce_max_sync(0xffffffffu, h2);
            unsigned c2r = __reduce_max_sync(0xffffffffu, (h2 == m2) ? (unsigned)contrib : 0u);
            wk2 = ((u64)m2 << 32) | (u64)c2r;
        }
    }
}

// ---------------------------------------------------------------------------
// Gather + pointwise 2-layer MLP + output assembly.
// IDENT=true: downsample row index == output row index (nested-FPS theorem).
// ---------------------------------------------------------------------------
template <int CPREV, int F, bool REPEAT, bool IDENT>
__global__ __launch_bounds__(256)
void mlp_kernel(const float* __restrict__ in, const int* __restrict__ idx,
                const float* __restrict__ w1, const float* __restrict__ b1,
                const float* __restrict__ w2, const float* __restrict__ b2,
                float* __restrict__ out, int n_in, int npoints)
{
    constexpr int PPB = 256 / F;
    constexpr int CIN = REPEAT ? 2 * CPREV : CPREV;

    __shared__ float row[PPB][CPREV];
    __shared__ float hsm[PPB][F];

    const int t  = threadIdx.x;
    const int lp = t / F;
    const int g  = t % F;
    const int gp = blockIdx.x * PPB + lp;
    const int b  = gp / npoints;
    const int pt = gp % npoints;

    const int src = IDENT ? pt : idx[b * npoints + pt];
    const float* r = in + ((size_t)b * n_in + src) * CPREV;
    if (g < CPREV) row[lp][g] = r[g];
    __syncthreads();

    float acc = b1[g];
#pragma unroll
    for (int c = 0; c < CIN; ++c)
        acc += row[lp][c % CPREV] * w1[c * F + g];
    hsm[lp][g] = fmaxf(acc, 0.0f);
    __syncthreads();

    float o = b2[g];
#pragma unroll
    for (int j = 0; j < F; ++j)
        o += hsm[lp][j] * w2[j * F + g];

    float* orow = out + ((size_t)b * npoints + pt) * F;
    orow[g] = (g < 3) ? row[lp][g] : o;
}

// ---------------------------------------------------------------------------
// Launch
// ---------------------------------------------------------------------------
extern "C" void kernel_launch(void* const* d_in, const int* in_sizes, int n_in_cnt,
                              void* d_out, int out_size)
{
    (void)in_sizes; (void)n_in_cnt; (void)out_size;

    const float* pts  = (const float*)d_in[0];
    const float* w1_1 = (const float*)d_in[1];
    const float* b1_1 = (const float*)d_in[2];
    const float* w2_1 = (const float*)d_in[3];
    const float* b2_1 = (const float*)d_in[4];
    const float* w1_2 = (const float*)d_in[5];
    const float* b1_2 = (const float*)d_in[6];
    const float* w2_2 = (const float*)d_in[7];
    const float* b2_2 = (const float*)d_in[8];
    const float* w1_3 = (const float*)d_in[9];
    const float* b1_3 = (const float*)d_in[10];
    const float* w2_3 = (const float*)d_in[11];
    const float* b2_3 = (const float*)d_in[12];
    const float* w1_4 = (const float*)d_in[13];
    const float* b1_4 = (const float*)d_in[14];
    const float* w2_4 = (const float*)d_in[15];
    const float* b2_4 = (const float*)d_in[16];

    float* out = (float*)d_out;
    const int B = 8;
    float* f1 = out;                        // [8,4096,16]
    float* f2 = out + 8 * 4096 * 16;        // [8,2048,32]
    float* f3 = f2 + 8 * 2048 * 32;         // [8,1024,64]
    float* f4 = f3 + 8 * 1024 * 64;         // [8, 512,128]

    static int*    idx_buf = nullptr;
    static float4* sort_buf = nullptr;
    if (!idx_buf)  cudaGetSymbolAddress((void**)&idx_buf,  g_fps_idx);
    if (!sort_buf) cudaGetSymbolAddress((void**)&sort_buf, g_sorted);

    static bool attr_done = false;
    if (!attr_done) {
        cudaFuncSetAttribute(fps_kernel<8192>,
                             cudaFuncAttributeMaxDynamicSharedMemorySize, 8192 * 16);
        attr_done = true;
    }

    // Slot shims: launch indices 0-2, so ncu's fixed capture slot (index 3)
    // lands on the level-1 FPS kernel.
    probe_align_kernel<<<1, 32>>>();
    probe_align_kernel<<<1, 32>>>();
    probe_align_kernel<<<1, 32>>>();

    // ---- Level 1: 8192 -> 4096 — the ONLY FPS run ----
    fps_kernel<8192><<<B, 512, 8192 * 16>>>(pts, 3, 4096, idx_buf, sort_buf);
    mlp_kernel<3, 16, true, false><<<(B * 4096) / 16, 256>>>(
        pts, idx_buf, w1_1, b1_1, w2_1, b2_1, f1, 8192, 4096);

    // ---- Levels 2-4: nested-FPS theorem -> identity downsample ----
    mlp_kernel<16, 32, false, true><<<(B * 2048) / 8, 256>>>(
        f1, idx_buf, w1_2, b1_2, w2_2, b2_2, f2, 4096, 2048);

    mlp_kernel<32, 64, false, true><<<(B * 1024) / 4, 256>>>(
        f2, idx_buf, w1_3, b1_3, w2_3, b2_3, f3, 2048, 1024);

    mlp_kernel<64, 128, false, true><<<(B * 512) / 2, 256>>>(
        f3, idx_buf, w1_4, b1_4, w2_4, b2_4, f4, 1024, 512);
}

// round 17
// speedup vs baseline: 6.5235x; 1.7511x over previous
#include <cuda_runtime.h>
#include <cstdint>

// ---------------------------------------------------------------------------
// Scratch
// ---------------------------------------------------------------------------
__device__ int    g_fps_idx[8 * 4096];
__device__ float4 g_sorted[8 * 8192];     // per-batch spatially sorted points

typedef unsigned long long u64;

// Packed f32x2 add (per-lane IEEE rn — proven bitwise == scalar FADD in R6)
__device__ __forceinline__ u64 pack2(float a, float b) {
    u64 r; asm("mov.b64 %0, {%1, %2};" : "=l"(r) : "f"(a), "f"(b)); return r;
}
__device__ __forceinline__ void unpack2(u64 v, float& a, float& b) {
    asm("mov.b64 {%0, %1}, %2;" : "=f"(a), "=f"(b) : "l"(v));
}
__device__ __forceinline__ u64 add2(u64 a, u64 b) {
    u64 r; asm("add.rn.f32x2 %0, %1, %2;" : "=l"(r) : "l"(a), "l"(b)); return r;
}

// 8x8x8 Morton cell over [-4, 4]
__device__ __forceinline__ int cell_of(float x, float y, float z) {
    int cx = min(max((int)(x + 4.0f), 0), 7);
    int cy = min(max((int)(y + 4.0f), 0), 7);
    int cz = min(max((int)(z + 4.0f), 0), 7);
    return (cx & 1) | ((cy & 1) << 1) | ((cz & 1) << 2)
         | (((cx >> 1) & 1) << 3) | (((cy >> 1) & 1) << 4) | (((cz >> 1) & 1) << 5)
         | ((cx >> 2) << 6) | ((cy >> 2) << 7) | ((cz >> 2) << 8);
}

// ---------------------------------------------------------------------------
// Level-1 FPS: 512 threads (16 warps), K=16 pts/thread — the bit-proven R12
// kernel with one preamble fix: the 512-cell prefix scan is warp-parallel
// (shfl scans + warp-sum combine) instead of a serial thread-0 loop
// (~10 us of dependent LDS/ADD/STS latency removed; offs[] values are
// identical, so the scatter and all downstream bits are unchanged).
//
// Iteration skeleton (measured floor ~650 cyc): publish cached warp key
// (STS.64) -> __syncthreads -> stage-2 redux over 16 keys -> winner coords
// (LDS.128) -> exact warp-bbox skip test -> (rare) update + stage-1 redux.
//
// Exactness ledger:
//  * distance math: packed-add subtraction == scalar FADD (R6-proven),
//    verbatim scalar dx*dx+dy*dy+dz*dz contraction, fminf chain.
//  * tie-break: (value desc, orig idx asc) via value-bits redux + complement
//    redux == jnp.argmax first-occurrence (R7/R12-validated); per-thread
//    insertion sort by orig idx restores within-thread tie order.
//  * skip test: monotone a*a+b*b+c*c bbox argument (R8-proven); the winner's
//    warp always fails (mind2 = 0) so it always refreshes.
//  * NESTED-FPS THEOREM (R12-proven): levels 2-4 FPS == identity.
// ---------------------------------------------------------------------------
template <int N>
__global__ __launch_bounds__(512, 1)
void fps_kernel(const float* __restrict__ pts, int C, int npoints,
                int* __restrict__ idx_out, float4* __restrict__ sorted_g)
{
    constexpr int T = 512, NW = 16, K = 16, KP = 8;

    extern __shared__ float4 sxyz[];          // N entries, ORIGINAL order
    __shared__ u64 rkeypub[2][NW];
    __shared__ int hist[512];
    __shared__ int offs[512];
    __shared__ int wsum[NW];

    const int b    = blockIdx.x;
    const int t    = threadIdx.x;
    const int lane = t & 31;
    const int wid  = t >> 5;

    const float* base = pts + (size_t)b * N * C;
    float4* sorted = sorted_g + (size_t)b * N;

    // ---- load orig-order copy + cell histogram ----
    hist[t] = 0;
    __syncthreads();
#pragma unroll
    for (int k = 0; k < K; ++k) {
        int i = t + k * T;
        const float* r = base + (size_t)i * C;
        float xx = r[0], yy = r[1], zz = r[2];
        sxyz[i] = make_float4(xx, yy, zz, 0.f);
        atomicAdd(&hist[cell_of(xx, yy, zz)], 1);
    }
    __syncthreads();

    // ---- warp-parallel exclusive prefix scan over 512 cells ----
    {
        int h = hist[t];
        int v = h;
#pragma unroll
        for (int o = 1; o < 32; o <<= 1) {
            int n = __shfl_up_sync(0xffffffffu, v, o);
            if (lane >= o) v += n;
        }
        if (lane == 31) wsum[wid] = v;
        __syncthreads();
        if (wid == 0) {
            int s = (lane < NW) ? wsum[lane] : 0;
#pragma unroll
            for (int o = 1; o < NW; o <<= 1) {
                int n = __shfl_up_sync(0xffffffffu, s, o);
                if (lane >= o) s += n;
            }
            if (lane < NW) wsum[lane] = s;
        }
        __syncthreads();
        int wbase = (wid > 0) ? wsum[wid - 1] : 0;
        offs[t] = wbase + v - h;              // exclusive prefix
    }
    __syncthreads();

    // ---- scatter to sorted global scratch (orig idx in .w) ----
#pragma unroll
    for (int k = 0; k < K; ++k) {
        int i = t + k * T;
        float4 q = sxyz[i];
        int pos = atomicAdd(&offs[cell_of(q.x, q.y, q.z)], 1);
        sorted[pos] = make_float4(q.x, q.y, q.z, __int_as_float(i));
    }
    __syncthreads();

    // ---- load my sorted points ----
    float xr[K], yr[K], zr[K], d[K];
    unsigned cf[K];                           // comp13 = 8191 - orig_idx
#pragma unroll
    for (int k = 0; k < K; ++k) {
        int slot = wid * (32 * K) + k * 32 + lane;
        float4 s = sorted[slot];
        xr[k] = s.x; yr[k] = s.y; zr[k] = s.z;
        cf[k] = 8191u - (unsigned)__float_as_int(s.w);
    }

    // ---- per-thread insertion sort by orig idx ascending ----
#pragma unroll
    for (int a = 1; a < K; ++a) {
#pragma unroll
        for (int c = a; c > 0; --c) {
            bool sw = cf[c] > cf[c - 1];
            float tf; unsigned tu;
            tf = sw ? xr[c] : xr[c - 1]; xr[c] = sw ? xr[c - 1] : xr[c]; xr[c - 1] = tf;
            tf = sw ? yr[c] : yr[c - 1]; yr[c] = sw ? yr[c - 1] : yr[c]; yr[c - 1] = tf;
            tf = sw ? zr[c] : zr[c - 1]; zr[c] = sw ? zr[c - 1] : zr[c]; zr[c - 1] = tf;
            tu = sw ? cf[c] : cf[c - 1]; cf[c] = sw ? cf[c - 1] : cf[c]; cf[c - 1] = tu;
        }
    }

    // ---- per-warp bbox ----
    float mnx = 1e30f, mny = 1e30f, mnz = 1e30f;
    float mxx = -1e30f, mxy = -1e30f, mxz = -1e30f;
#pragma unroll
    for (int k = 0; k < K; ++k) {
        mnx = fminf(mnx, xr[k]); mxx = fmaxf(mxx, xr[k]);
        mny = fminf(mny, yr[k]); mxy = fmaxf(mxy, yr[k]);
        mnz = fminf(mnz, zr[k]); mxz = fmaxf(mxz, zr[k]);
    }
#pragma unroll
    for (int o = 16; o > 0; o >>= 1) {
        mnx = fminf(mnx, __shfl_xor_sync(0xffffffffu, mnx, o));
        mny = fminf(mny, __shfl_xor_sync(0xffffffffu, mny, o));
        mnz = fminf(mnz, __shfl_xor_sync(0xffffffffu, mnz, o));
        mxx = fmaxf(mxx, __shfl_xor_sync(0xffffffffu, mxx, o));
        mxy = fmaxf(mxy, __shfl_xor_sync(0xffffffffu, mxy, o));
        mxz = fmaxf(mxz, __shfl_xor_sync(0xffffffffu, mxz, o));
    }

    // ---- packed coord registers ----
    u64 xp[KP], yp[KP], zp[KP];
#pragma unroll
    for (int j = 0; j < KP; ++j) {
        xp[j] = pack2(xr[2 * j], xr[2 * j + 1]);
        yp[j] = pack2(yr[2 * j], yr[2 * j + 1]);
        zp[j] = pack2(zr[2 * j], zr[2 * j + 1]);
    }

    if (t == 0) idx_out[b * npoints] = 0;

    // ---- initial distances to point 0 (verbatim scalar) + argmax ----
    float    bv = -1.0f;
    unsigned bc = 0;
    {
        float4 q = sxyz[0];
        float px = q.x, py = q.y, pz = q.z;
#pragma unroll
        for (int k = 0; k < K; ++k) {
            float dx = xr[k] - px, dy = yr[k] - py, dz = zr[k] - pz;
            d[k] = dx * dx + dy * dy + dz * dz;
            if (d[k] > bv) { bv = d[k]; bc = cf[k]; }
        }
    }
    unsigned cm, ccomp;
    {
        unsigned ub = __float_as_uint(bv);
        cm = __reduce_max_sync(0xffffffffu, ub);
        unsigned cand = (ub == cm) ? bc : 0u;
        ccomp = __reduce_max_sync(0xffffffffu, cand);
    }

    // pack comp13 2x16-bit per register for the update loop
    unsigned cpk[KP];
#pragma unroll
    for (int j = 0; j < KP; ++j) cpk[j] = cf[2 * j] | (cf[2 * j + 1] << 16);

    for (int it = 1; it < npoints; ++it) {
        const int p = it & 1;
        if (lane == 0) rkeypub[p][wid] = ((u64)cm << 32) | (u64)ccomp;
        __syncthreads();

        // stage 2: reduce the 16 warp keys (LDS.64)
        u64 kk = rkeypub[p][lane & (NW - 1)];
        unsigned vw = (unsigned)(kk >> 32);
        unsigned iw = (unsigned)kk;
        unsigned m2 = __reduce_max_sync(0xffffffffu, vw);
        unsigned c2 = (vw == m2) ? iw : 0u;
        unsigned comp2 = __reduce_max_sync(0xffffffffu, c2);
        int bsel = 8191 - (int)comp2;               // ORIGINAL index

        if (t == 0) idx_out[b * npoints + it] = bsel;

        float4 q = sxyz[bsel];
        float px = q.x, py = q.y, pz = q.z;

        // warp-uniform exact bbox skip test
        float ax = fmaxf(fmaxf(mnx - px, px - mxx), 0.f);
        float ay = fmaxf(fmaxf(mny - py, py - mxy), 0.f);
        float az = fmaxf(fmaxf(mnz - pz, pz - mxz), 0.f);
        float mind2 = ax * ax + ay * ay + az * az;

        if (mind2 < __uint_as_float(cm)) {
            bv = -1.0f; bc = 0;
            const u64 nxp = pack2(-px, -px);
            const u64 nyp = pack2(-py, -py);
            const u64 nzp = pack2(-pz, -pz);
#pragma unroll
            for (int j = 0; j < KP; ++j) {
                float dx0, dx1, dy0, dy1, dz0, dz1;
                unpack2(add2(xp[j], nxp), dx0, dx1);
                unpack2(add2(yp[j], nyp), dy0, dy1);
                unpack2(add2(zp[j], nzp), dz0, dz1);
                float nd0 = dx0 * dx0 + dy0 * dy0 + dz0 * dz0;
                float nd1 = dx1 * dx1 + dy1 * dy1 + dz1 * dz1;
                float dk0 = fminf(d[2 * j],     nd0);
                float dk1 = fminf(d[2 * j + 1], nd1);
                d[2 * j]     = dk0;
                d[2 * j + 1] = dk1;
                if (dk0 > bv) { bv = dk0; bc = cpk[j] & 0xFFFFu; }
                if (dk1 > bv) { bv = dk1; bc = cpk[j] >> 16; }
            }
            unsigned ub = __float_as_uint(bv);
            cm = __reduce_max_sync(0xffffffffu, ub);
            unsigned cand = (ub == cm) ? bc : 0u;
            ccomp = __reduce_max_sync(0xffffffffu, cand);
        }
        // else: skip — d unchanged, cached (cm, ccomp) still exact
    }
}

// ---------------------------------------------------------------------------
// Gather + pointwise 2-layer MLP + output assembly.
// IDENT=true: downsample row index == output row index (nested-FPS theorem).
// ---------------------------------------------------------------------------
template <int CPREV, int F, bool REPEAT, bool IDENT>
__global__ __launch_bounds__(256)
void mlp_kernel(const float* __restrict__ in, const int* __restrict__ idx,
                const float* __restrict__ w1, const float* __restrict__ b1,
                const float* __restrict__ w2, const float* __restrict__ b2,
                float* __restrict__ out, int n_in, int npoints)
{
    constexpr int PPB = 256 / F;
    constexpr int CIN = REPEAT ? 2 * CPREV : CPREV;

    __shared__ float row[PPB][CPREV];
    __shared__ float hsm[PPB][F];

    const int t  = threadIdx.x;
    const int lp = t / F;
    const int g  = t % F;
    const int gp = blockIdx.x * PPB + lp;
    const int b  = gp / npoints;
    const int pt = gp % npoints;

    const int src = IDENT ? pt : idx[b * npoints + pt];
    const float* r = in + ((size_t)b * n_in + src) * CPREV;
    if (g < CPREV) row[lp][g] = r[g];
    __syncthreads();

    float acc = b1[g];
#pragma unroll
    for (int c = 0; c < CIN; ++c)
        acc += row[lp][c % CPREV] * w1[c * F + g];
    hsm[lp][g] = fmaxf(acc, 0.0f);
    __syncthreads();

    float o = b2[g];
#pragma unroll
    for (int j = 0; j < F; ++j)
        o += hsm[lp][j] * w2[j * F + g];

    float* orow = out + ((size_t)b * npoints + pt) * F;
    orow[g] = (g < 3) ? row[lp][g] : o;
}

// ---------------------------------------------------------------------------
// Launch
// ---------------------------------------------------------------------------
extern "C" void kernel_launch(void* const* d_in, const int* in_sizes, int n_in_cnt,
                              void* d_out, int out_size)
{
    (void)in_sizes; (void)n_in_cnt; (void)out_size;

    const float* pts  = (const float*)d_in[0];
    const float* w1_1 = (const float*)d_in[1];
    const float* b1_1 = (const float*)d_in[2];
    const float* w2_1 = (const float*)d_in[3];
    const float* b2_1 = (const float*)d_in[4];
    const float* w1_2 = (const float*)d_in[5];
    const float* b1_2 = (const float*)d_in[6];
    const float* w2_2 = (const float*)d_in[7];
    const float* b2_2 = (const float*)d_in[8];
    const float* w1_3 = (const float*)d_in[9];
    const float* b1_3 = (const float*)d_in[10];
    const float* w2_3 = (const float*)d_in[11];
    const float* b2_3 = (const float*)d_in[12];
    const float* w1_4 = (const float*)d_in[13];
    const float* b1_4 = (const float*)d_in[14];
    const float* w2_4 = (const float*)d_in[15];
    const float* b2_4 = (const float*)d_in[16];

    float* out = (float*)d_out;
    const int B = 8;
    float* f1 = out;                        // [8,4096,16]
    float* f2 = out + 8 * 4096 * 16;        // [8,2048,32]
    float* f3 = f2 + 8 * 2048 * 32;         // [8,1024,64]
    float* f4 = f3 + 8 * 1024 * 64;         // [8, 512,128]

    static int*    idx_buf = nullptr;
    static float4* sort_buf = nullptr;
    if (!idx_buf)  cudaGetSymbolAddress((void**)&idx_buf,  g_fps_idx);
    if (!sort_buf) cudaGetSymbolAddress((void**)&sort_buf, g_sorted);

    static bool attr_done = false;
    if (!attr_done) {
        cudaFuncSetAttribute(fps_kernel<8192>,
                             cudaFuncAttributeMaxDynamicSharedMemorySize, 8192 * 16);
        attr_done = true;
    }

    // ---- Level 1: 8192 -> 4096 — the ONLY FPS run ----
    fps_kernel<8192><<<B, 512, 8192 * 16>>>(pts, 3, 4096, idx_buf, sort_buf);
    mlp_kernel<3, 16, true, false><<<(B * 4096) / 16, 256>>>(
        pts, idx_buf, w1_1, b1_1, w2_1, b2_1, f1, 8192, 4096);

    // ---- Levels 2-4: nested-FPS theorem -> identity downsample ----
    mlp_kernel<16, 32, false, true><<<(B * 2048) / 8, 256>>>(
        f1, idx_buf, w1_2, b1_2, w2_2, b2_2, f2, 4096, 2048);

    mlp_kernel<32, 64, false, true><<<(B * 1024) / 4, 256>>>(
        f2, idx_buf, w1_3, b1_3, w2_3, b2_3, f3, 2048, 1024);

    mlp_kernel<64, 128, false, true><<<(B * 512) / 2, 256>>>(
        f3, idx_buf, w1_4, b1_4, w2_4, b2_4, f4, 1024, 512);
}